// round 16
// baseline (speedup 1.0000x reference)
#include <cuda_runtime.h>
#include <math.h>

#define BATCH 16
#define NSAMP 72000
#define TOTF  2039   // 17+33+65+129+257+513+1025

// One fused scratch blob -> single memset clears everything:
// [0,TOTF) = s1, [TOTF,2*TOTF) = s2, [2*TOTF] = acc, [2*TOTF+1] = done flag.
__device__ double g_blob[2 * TOTF + 2];
#define g_s1 (g_blob)
#define g_s2 (g_blob + TOTF)

__host__ __device__ constexpr int ilog2c(int n) { return (n <= 1) ? 0 : 1 + ilog2c(n >> 1); }

// Blocks runtime constant folding while preserving exact double bits.
__device__ __forceinline__ double opaque_d(double x) { volatile double t = x; return t; }

__device__ __forceinline__ float2 cadd(float2 a, float2 b) { return make_float2(a.x + b.x, a.y + b.y); }
__device__ __forceinline__ float2 csub(float2 a, float2 b) { return make_float2(a.x - b.x, a.y - b.y); }
__device__ __forceinline__ float2 cmul(float2 a, float2 b) {
    return make_float2(a.x * b.x - a.y * b.y, a.x * b.y + a.y * b.x);
}

// Persistent one-wave grid: 148 SMs x 4 blocks/SM = 592 blocks.
// Pass counts after load {1,1,1,2,2,2,3} -> cost/elem {6.5,6.5,6.5,8.5,8.5,
// 8.5,10.5} -> shares {69,69,69,91,91,91,112} (sum 592).
#define NBLOCKS 592
#define SMEM_DYN (16384 + 8 * 2048 + 8 * 1032)
#define RQ 0.70710678118654752440f
#define C1 0.92387953251128675613f   // cos(pi/8)
#define S1 0.38268343236508977173f   // sin(pi/8)

__device__ __constant__ int c_soff[7] = {0, 17, 50, 115, 244, 501, 1014};
__device__ __constant__ int c_T[7]    = {9001, 4501, 2251, 1126, 563, 282, 141};

template<int S>
__device__ __forceinline__ int swz(int i) { return i ^ (((i >> S) ^ (i >> 4)) & 15); }

// 8-point DFT, natural-order outputs, in place.
__device__ __forceinline__ void dft8(float2* v) {
    const float2 t0 = cadd(v[0], v[4]), t1 = csub(v[0], v[4]);
    const float2 t2 = cadd(v[2], v[6]), t3 = csub(v[2], v[6]);
    const float2 E0 = cadd(t0, t2), E2 = csub(t0, t2);
    const float2 E1 = make_float2(t1.x + t3.y, t1.y - t3.x);
    const float2 E3 = make_float2(t1.x - t3.y, t1.y + t3.x);
    const float2 u0 = cadd(v[1], v[5]), u1 = csub(v[1], v[5]);
    const float2 u2 = cadd(v[3], v[7]), u3 = csub(v[3], v[7]);
    const float2 O0 = cadd(u0, u2), O2 = csub(u0, u2);
    const float2 O1 = make_float2(u1.x + u3.y, u1.y - u3.x);
    const float2 O3 = make_float2(u1.x - u3.y, u1.y + u3.x);
    const float2 w1O1 = make_float2(RQ * (O1.x + O1.y), RQ * (O1.y - O1.x));   // (1-i)r*O1
    const float2 w2O2 = make_float2(O2.y, -O2.x);                               // -i*O2
    const float2 w3O3 = make_float2(RQ * (O3.y - O3.x), -RQ * (O3.x + O3.y));  // (-1-i)r*O3
    v[0] = cadd(E0, O0);   v[4] = csub(E0, O0);
    v[1] = cadd(E1, w1O1); v[5] = csub(E1, w1O1);
    v[2] = cadd(E2, w2O2); v[6] = csub(E2, w2O2);
    v[3] = cadd(E3, w3O3); v[7] = csub(E3, w3O3);
}

// Radix-4 SMEM pass: stages (L, 2L). t2 = w_{2L}^j from LDS, w_L^j = t2^2.
template<int NFFT, int L, int TPF, int S>
__device__ __forceinline__ void radix4_pass(float2* buf, const float2* tw, int base, int ltid) {
    constexpr int BPT = (NFFT / 4) / TPF;
#pragma unroll
    for (int r = 0; r < BPT; r++) {
        const int idx = ltid + r * TPF;
        const int j   = idx & (L / 2 - 1);
        const int g   = idx / (L / 2);
        const int p   = base + g * (2 * L) + j;
        float2 a0 = buf[swz<S>(p)];
        float2 a1 = buf[swz<S>(p + L / 2)];
        float2 a2 = buf[swz<S>(p + L)];
        float2 a3 = buf[swz<S>(p + 3 * L / 2)];
        const float2 t2 = tw[j * (NFFT / (2 * L))];  // w_{2L}^j
        const float2 t1 = cmul(t2, t2);              // w_L^j
        const float2 u1 = cmul(t1, a1), u3 = cmul(t1, a3);
        const float2 c0 = cadd(a0, u1), c1 = csub(a0, u1);
        const float2 c2 = cadd(a2, u3), c3 = csub(a2, u3);
        const float2 v2 = cmul(t2, c2), v3 = cmul(t2, c3);
        buf[swz<S>(p)]             = cadd(c0, v2);
        buf[swz<S>(p + L)]         = csub(c0, v2);
        buf[swz<S>(p + L / 2)]     = make_float2(c1.x + v3.y, c1.y - v3.x);  // c1 - i*v3
        buf[swz<S>(p + 3 * L / 2)] = make_float2(c1.x - v3.y, c1.y + v3.x);  // c1 + i*v3
    }
}

// Radix-8 SMEM pass: stages (L, 2L, 4L) in one round trip.
// t4 = w_{4L}^j (one LDS); t2 = t4^2, t1 = t4^4 (exact identities).
template<int NFFT, int L, int TPF, int S>
__device__ __forceinline__ void radix8_pass(float2* buf, const float2* tw, int base, int ltid) {
    constexpr int BPT = (NFFT / 8) / TPF;
#pragma unroll
    for (int r = 0; r < BPT; r++) {
        const int idx = ltid + r * TPF;
        const int j   = idx & (L / 2 - 1);
        const int g   = idx / (L / 2);
        const int p   = base + g * (4 * L) + j;
        float2 b[8];
#pragma unroll
        for (int m = 0; m < 8; m++) b[m] = buf[swz<S>(p + m * (L / 2))];
        const float2 t4 = tw[j * (NFFT / (4 * L))];  // w_{4L}^j
        const float2 t2 = cmul(t4, t4);              // w_{2L}^j
        const float2 t1 = cmul(t2, t2);              // w_L^j
        float2 c[8];
#pragma unroll
        for (int m = 0; m < 4; m++) {
            const float2 u = cmul(t1, b[2 * m + 1]);
            c[2 * m]     = cadd(b[2 * m], u);
            c[2 * m + 1] = csub(b[2 * m], u);
        }
        float2 d[8];
        {
            const float2 tb = make_float2(t2.y, -t2.x);  // -i*t2
            float2 v;
            v = cmul(t2, c[2]); d[0] = cadd(c[0], v); d[2] = csub(c[0], v);
            v = cmul(tb, c[3]); d[1] = cadd(c[1], v); d[3] = csub(c[1], v);
            v = cmul(t2, c[6]); d[4] = cadd(c[4], v); d[6] = csub(c[4], v);
            v = cmul(tb, c[7]); d[5] = cadd(c[5], v); d[7] = csub(c[5], v);
        }
        {
            const float2 f1 = make_float2(RQ * (t4.x + t4.y), RQ * (t4.y - t4.x));   // t4*(1-i)r
            const float2 f2 = make_float2(t4.y, -t4.x);                               // t4*(-i)
            const float2 f3 = make_float2(RQ * (t4.y - t4.x), -RQ * (t4.x + t4.y));  // t4*(-1-i)r
            float2 v;
            v = cmul(t4, d[4]); buf[swz<S>(p)]             = cadd(d[0], v); buf[swz<S>(p + 4*(L/2))] = csub(d[0], v);
            v = cmul(f1, d[5]); buf[swz<S>(p + 1*(L/2))]   = cadd(d[1], v); buf[swz<S>(p + 5*(L/2))] = csub(d[1], v);
            v = cmul(f2, d[6]); buf[swz<S>(p + 2*(L/2))]   = cadd(d[2], v); buf[swz<S>(p + 6*(L/2))] = csub(d[2], v);
            v = cmul(f3, d[7]); buf[swz<S>(p + 3*(L/2))]   = cadd(d[3], v); buf[swz<S>(p + 7*(L/2))] = csub(d[3], v);
        }
    }
}

// ---------------------------------------------------------------------------
// Packed complex FFT (z = x + i*x_hat) over all frames of one scale.
// Load fuses windowing + first 3 stages (8-pt DFT); for N=128 and N=1024,
// first 4 stages (16-pt DFT) -> one fewer SMEM round trip (128: 2 r4 passes
// collapse to 1 r8 pass). XOR bank swizzle on buf. TPF = NFFT/8;
// frame-scoped synchronization (warp-level for N<=256).
// ---------------------------------------------------------------------------
template<int NFFT, int OFF, int NBLK>
__device__ __forceinline__ void stft_body(const float* __restrict__ x,
                                          const float* __restrict__ xh,
                                          int blk, char* raw) {
    constexpr int  HOP    = NFFT / 4;
    constexpr int  PAD    = NFFT / 2;
    constexpr int  T      = 1 + NSAMP / HOP;
    constexpr int  TOTAL  = BATCH * T;
    constexpr int  F      = NFFT / 2 + 1;
    constexpr int  LOG2N  = ilog2c(NFFT);
    constexpr int  TPB    = 256;
    constexpr int  TPF    = (NFFT / 8 > TPB) ? TPB : (NFFT / 8);
    constexpr int  FPB    = TPB / TPF;
    constexpr int  KPT    = (F + TPF - 1) / TPF;
    constexpr int  BUFSZ  = FPB * NFFT;                // == 2048 for all scales
    static_assert(BUFSZ == 2048, "layout assumes BUFSZ==2048");
    constexpr int  S      = ilog2c(BUFSZ) - 4;
    constexpr bool LOAD16 = (LOG2N == 7) || (LOG2N == 10);  // 16-pt load stage

    float2* buf  = (float2*)raw;
    float2* tw   = (float2*)(raw + 16384);
    float*  win  = (float*)(raw + 16384 + 4 * NFFT);
    float*  red1 = (float*)(raw + 16384 + 8 * NFFT);
    float*  red2 = (float*)(raw + 16384 + 8 * NFFT + 4 * F);

    const int tid  = threadIdx.x;
    const int slot = tid / TPF;
    const int ltid = tid % TPF;
    const int base = slot * NFFT;

    auto sw = [](int i) { return swz<S>(i); };

    auto fsync = [&]() {
        if constexpr (TPF <= 32) { __syncwarp(); }
        else if constexpr (TPF >= TPB) { __syncthreads(); }
        else { asm volatile("bar.sync %0, %1;" :: "r"(slot + 1), "r"(TPF) : "memory"); }
    };

    // Twiddles: tw[t] = exp(-2*pi*i*t/N). Window: periodic hann / sqrt(0.375*N).
    const float rnorm = rsqrtf(0.375f * (float)NFFT);
    for (int t = tid; t < NFFT / 2; t += TPB) {
        float s, c;
        sincospif(2.0f * (float)t / (float)NFFT, &s, &c);
        tw[t] = make_float2(c, -s);
    }
    for (int t = tid; t < NFFT; t += TPB) {
        win[t] = (0.5f - 0.5f * cospif(2.0f * (float)t / (float)NFFT)) * rnorm;
    }
    for (int t = tid; t < F; t += TPB) { red1[t] = 0.0f; red2[t] = 0.0f; }

    float acc1[KPT], acc2[KPT];
#pragma unroll
    for (int r = 0; r < KPT; r++) { acc1[r] = 0.0f; acc2[r] = 0.0f; }

    __syncthreads();

    for (int fb = blk * FPB; fb < TOTAL; fb += NBLK * FPB) {
        const int gf = fb + slot;
        const bool valid = (gf < TOTAL);

        int start = 0;
        const float *xb = x, *xhb = xh;
        if (valid) {
            const int bb = gf / T;
            const int t0 = gf - bb * T;
            start = t0 * HOP - PAD;
            xb  = x  + bb * NSAMP;
            xhb = xh + bb * NSAMP;
        }

        auto load_one = [&](int tt) -> float2 {
            int s = start + tt;
            s = (s < 0) ? -s : s;                        // reflect left
            s = (s >= NSAMP) ? (2 * NSAMP - 2 - s) : s;  // reflect right
            const float wv = win[tt];
            return make_float2(xb[s] * wv, xhb[s] * wv);
        };

        if constexpr (!LOAD16) {
            // Load + window + 8-point DFT (stages 2,4,8).
            if (valid) {
                const int idx = ltid;                 // [0, N/8), TPF == N/8
                const int g   = (int)(__brev((unsigned)idx) >> (32 - (LOG2N - 3)));
                float2 a[8];
#pragma unroll
                for (int m = 0; m < 8; m++) a[m] = load_one(idx + m * (NFFT / 8));
                dft8(a);
                const int wb = base + 8 * g;
#pragma unroll
                for (int k = 0; k < 8; k++) buf[sw(wb + k)] = a[k];
            }
        } else {
            // Load + window + 16-point DFT (stages 2,4,8,16). N/16 groups,
            // handled by ltid < N/16 (half the frame's threads).
            if (valid && ltid < NFFT / 16) {
                const int idx = ltid;                 // [0, N/16)
                const int g   = (int)(__brev((unsigned)idx) >> (32 - (LOG2N - 4)));
                float2 ev[8], od[8];
#pragma unroll
                for (int m = 0; m < 8; m++) ev[m] = load_one(idx + m * (NFFT / 8));
                dft8(ev);
#pragma unroll
                for (int m = 0; m < 8; m++) od[m] = load_one(idx + NFFT / 16 + m * (NFFT / 8));
                dft8(od);
                // X[k] = ev[k] + w16^k od[k]; X[k+8] = ev[k] - w16^k od[k]
                const int wb = base + 16 * g;
                float2 t;
                buf[sw(wb + 0)] = cadd(ev[0], od[0]);
                buf[sw(wb + 8)] = csub(ev[0], od[0]);
                t = cmul(make_float2(C1, -S1), od[1]);
                buf[sw(wb + 1)] = cadd(ev[1], t);  buf[sw(wb + 9)]  = csub(ev[1], t);
                t = make_float2(RQ * (od[2].x + od[2].y), RQ * (od[2].y - od[2].x));
                buf[sw(wb + 2)] = cadd(ev[2], t);  buf[sw(wb + 10)] = csub(ev[2], t);
                t = cmul(make_float2(S1, -C1), od[3]);
                buf[sw(wb + 3)] = cadd(ev[3], t);  buf[sw(wb + 11)] = csub(ev[3], t);
                t = make_float2(od[4].y, -od[4].x);
                buf[sw(wb + 4)] = cadd(ev[4], t);  buf[sw(wb + 12)] = csub(ev[4], t);
                t = cmul(make_float2(-S1, -C1), od[5]);
                buf[sw(wb + 5)] = cadd(ev[5], t);  buf[sw(wb + 13)] = csub(ev[5], t);
                t = make_float2(RQ * (od[6].y - od[6].x), -RQ * (od[6].x + od[6].y));
                buf[sw(wb + 6)] = cadd(ev[6], t);  buf[sw(wb + 14)] = csub(ev[6], t);
                t = cmul(make_float2(-C1, -S1), od[7]);
                buf[sw(wb + 7)] = cadd(ev[7], t);  buf[sw(wb + 15)] = csub(ev[7], t);
            }
        }
        fsync();

        // Remaining stages: radix-8 / radix-4 passes.
        if constexpr (LOG2N == 5) {
            radix4_pass<NFFT, 16, TPF, S>(buf, tw, base, ltid); fsync();
        } else if constexpr (LOG2N == 6) {
            radix8_pass<NFFT, 16, TPF, S>(buf, tw, base, ltid); fsync();
        } else if constexpr (LOG2N == 7) {
            // load16 retired stages 2..16; one radix-8 covers 32,64,128
            radix8_pass<NFFT, 32, TPF, S>(buf, tw, base, ltid); fsync();
        } else if constexpr (LOG2N == 8) {
            radix8_pass<NFFT, 16, TPF, S>(buf, tw, base, ltid); fsync();
            radix4_pass<NFFT, 128, TPF, S>(buf, tw, base, ltid); fsync();
        } else if constexpr (LOG2N == 9) {
            radix8_pass<NFFT, 16, TPF, S>(buf, tw, base, ltid); fsync();
            radix8_pass<NFFT, 128, TPF, S>(buf, tw, base, ltid); fsync();
        } else if constexpr (LOG2N == 10) {
            // load16 retired stages 2..16
            radix8_pass<NFFT, 32, TPF, S>(buf, tw, base, ltid); fsync();
            radix8_pass<NFFT, 256, TPF, S>(buf, tw, base, ltid); fsync();
        } else {
            radix8_pass<NFFT, 16, TPF, S>(buf, tw, base, ltid); fsync();
            radix8_pass<NFFT, 128, TPF, S>(buf, tw, base, ltid); fsync();
            radix4_pass<NFFT, 1024, TPF, S>(buf, tw, base, ltid); fsync();
        }

        // Unpack X (from x) and Xh (from x_hat), accumulate stats
        if (valid) {
#pragma unroll
            for (int r = 0; r < KPT; r++) {
                const int k = ltid + r * TPF;
                if (k <= NFFT / 2) {
                    const float2 zk = buf[sw(base + k)];
                    const float2 zn = buf[sw(base + ((NFFT - k) & (NFFT - 1)))];
                    const float ar = 0.5f * (zk.x + zn.x);
                    const float ai = 0.5f * (zk.y - zn.y);
                    const float br = 0.5f * (zk.y + zn.y);
                    const float bi = 0.5f * (zn.x - zk.x);
                    const float magA = sqrtf(ar * ar + ai * ai);
                    const float magB = sqrtf(br * br + bi * bi);
                    const float d = magB - magA;          // |Xh| - |X|
                    acc1[r] += fabsf(d);
                    acc2[r] += d * d;
                }
            }
        }
        fsync();   // protect buf before next load (frame-scoped)
    }

    // Block reduce: registers -> shared float
#pragma unroll
    for (int r = 0; r < KPT; r++) {
        const int k = ltid + r * TPF;
        if (k <= NFFT / 2) {
            atomicAdd(&red1[k], acc1[r]);
            atomicAdd(&red2[k], acc2[r]);
        }
    }
    __syncthreads();

    for (int k = tid; k < F; k += TPB) {
        atomicAdd(&g_s1[OFF + k], (double)red1[k]);
        atomicAdd(&g_s2[OFF + k], (double)red2[k]);
    }
}

// All 7 scales, one persistent wave; min 4 blocks/SM (<=64 regs).
// Shares: {69,69,69,91,91,91,112} (cost-balanced, sum 592).
__global__ void __launch_bounds__(256, 4)
fused_stft(const float* __restrict__ x, const float* __restrict__ xh) {
    extern __shared__ char raw[];
    const int b = blockIdx.x;
    if      (b <  69) stft_body<  32,    0,  69>(x, xh, b,       raw);
    else if (b < 138) stft_body<  64,   17,  69>(x, xh, b - 69,  raw);
    else if (b < 207) stft_body< 128,   50,  69>(x, xh, b - 138, raw);
    else if (b < 298) stft_body< 256,  115,  91>(x, xh, b - 207, raw);
    else if (b < 389) stft_body< 512,  244,  91>(x, xh, b - 298, raw);
    else if (b < 480) stft_body<1024,  501,  91>(x, xh, b - 389, raw);
    else              stft_body<2048, 1014, 112>(x, xh, b - 480, raw);
}

// ---------------------------------------------------------------------------
// Loss: 7 blocks (one per scale). fpts[0..64] via cheap fp64 exp2 (error ~2ulp
// vs >=1e-9 margins); index 65 keeps the bit-exact libdevice pow + the verified
// Nyquist flip in an otherwise-empty warp. Band-edge decisions unchanged.
// ---------------------------------------------------------------------------
__global__ void __launch_bounds__(256) loss_kernel(float* out) {
    const int s    = blockIdx.x;
    const int tid  = threadIdx.x;
    const int w    = tid >> 5;
    const int lane = tid & 31;
    const int NFFT = 32 << s;
    const int F    = NFFT / 2 + 1;

    __shared__ double fpts[66];
    __shared__ int2   sab[64];
    __shared__ double ssum;
    if (tid == 0) ssum = 0.0;

    const double melmax = 2595.0 * log10(1.0 + 12000.0 / 700.0);
    if (tid < 65) {
        const double e = melmax * (double)tid / 65.0 / 2595.0;
        fpts[tid] = 700.0 * (exp2(e * 3.3219280948873623478703194) - 1.0);
    } else if (tid == 96) {
        // index 65: exact libdevice pow expression (bit-identical to verified)
        fpts[65] = 700.0 * (pow(10.0, opaque_d(melmax * 65.0 / 65.0) / 2595.0) - 1.0);
    }
    __syncthreads();

    bool keep = false;
    if (tid < 64) {
        const int m = tid;
        const double step = 12000.0 / (double)(F - 1);
        const bool nyq_in = !(fpts[65] > 12000.0);   // flipped libdevice decision (verified)

        int a[2], b[2];   // [0] = band m, [1] = band m-1
        for (int q = 0; q < 2; q++) {
            const int mm = m - q;
            if (mm < 0) { a[q] = 0; b[q] = 0; continue; }
            const double lo = fpts[mm];
            int a0 = (int)floor(lo / step); if ((double)a0 * step <= lo) a0++;  // first f: f*step > lo
            if (a0 < 0) a0 = 0;
            int b0;
            if (mm + 2 == 65) {
                b0 = nyq_in ? F : (F - 1);
            } else {
                const double hi = fpts[mm + 2];
                b0 = (int)floor(hi / step); if ((double)b0 * step <  hi) b0++;  // last f+1: f*step < hi
                if (b0 > F) b0 = F;
            }
            a[q] = a0; b[q] = b0;
        }
        const bool nonempty = (b[0] > a[0]);
        const bool dup = (m > 0) && (a[0] == a[1]) && (b[0] == b[1]) && nonempty;
        keep = nonempty && !dup;
        sab[m] = keep ? make_int2(a[0], b[0]) : make_int2(0, 0);
    }
    const int nb = __syncthreads_count(keep ? 1 : 0);

    for (int cand = w; cand < 64; cand += 8) {
        const int2 ab = sab[cand];
        if (ab.y > ab.x) {
            double p1 = 0.0, p2 = 0.0;
            for (int f = ab.x + lane; f < ab.y; f += 32) {
                p1 += g_s1[c_soff[s] + f];
                p2 += g_s2[c_soff[s] + f];
            }
#pragma unroll
            for (int o = 16; o > 0; o >>= 1) {
                p1 += __shfl_down_sync(0xffffffffu, p1, o);
                p2 += __shfl_down_sync(0xffffffffu, p2, o);
            }
            if (lane == 0) {
                const double cnt = (double)(ab.y - ab.x) * (double)BATCH * (double)c_T[s];
                const double val = p1 / cnt + sqrt(p2 / cnt + 1e-8);
                atomicAdd(&ssum, val);
            }
        }
    }
    __syncthreads();

    if (tid == 0) {
        double* acc  = g_blob + 2 * TOTF;
        int*    done = (int*)(g_blob + 2 * TOTF + 1);
        const double contrib = ssum / (double)nb / 7.0;
        atomicAdd(acc, contrib);
        __threadfence();
        const int old = atomicAdd(done, 1);
        if (old == 6) {
            out[0] = (float)(*(volatile double*)acc);
        }
    }
}

extern "C" void kernel_launch(void* const* d_in, const int* in_sizes, int n_in,
                              void* d_out, int out_size) {
    const float* xh = (const float*)d_in[0];   // x_hat
    const float* x  = (const float*)d_in[1];   // x

    void* pb = nullptr;
    cudaGetSymbolAddress(&pb, g_blob);
    cudaMemsetAsync(pb, 0, (2 * TOTF + 2) * sizeof(double));

    fused_stft<<<NBLOCKS, 256, SMEM_DYN>>>(x, xh);
    loss_kernel<<<7, 256>>>((float*)d_out);
}

// round 17
// speedup vs baseline: 1.0441x; 1.0441x over previous
#include <cuda_runtime.h>
#include <math.h>

#define BATCH 16
#define NSAMP 72000
#define TOTF  2039   // 17+33+65+129+257+513+1025

// One fused scratch blob -> single memset clears everything:
// [0,TOTF) = s1, [TOTF,2*TOTF) = s2, [2*TOTF] = acc, [2*TOTF+1] = done flag.
__device__ double g_blob[2 * TOTF + 2];
#define g_s1 (g_blob)
#define g_s2 (g_blob + TOTF)

__host__ __device__ constexpr int ilog2c(int n) { return (n <= 1) ? 0 : 1 + ilog2c(n >> 1); }

// Blocks runtime constant folding while preserving exact double bits.
__device__ __forceinline__ double opaque_d(double x) { volatile double t = x; return t; }

__device__ __forceinline__ float2 cadd(float2 a, float2 b) { return make_float2(a.x + b.x, a.y + b.y); }
__device__ __forceinline__ float2 csub(float2 a, float2 b) { return make_float2(a.x - b.x, a.y - b.y); }
__device__ __forceinline__ float2 cmul(float2 a, float2 b) {
    return make_float2(a.x * b.x - a.y * b.y, a.x * b.y + a.y * b.x);
}

// Persistent one-wave grid: 148 SMs x 4 blocks/SM = 592 blocks.
// Cost weights {3,3,4,4,4,4.5,5}/27.5 (N=1024 discounted for its load16)
// -> shares {65,65,86,86,86,97,107} (sum 592).
#define NBLOCKS 592
#define SMEM_DYN (16384 + 8 * 2048 + 8 * 1032)
#define RQ 0.70710678118654752440f
#define C1 0.92387953251128675613f   // cos(pi/8)
#define S1 0.38268343236508977173f   // sin(pi/8)

__device__ __constant__ int c_soff[7] = {0, 17, 50, 115, 244, 501, 1014};
__device__ __constant__ int c_T[7]    = {9001, 4501, 2251, 1126, 563, 282, 141};

template<int S>
__device__ __forceinline__ int swz(int i) { return i ^ (((i >> S) ^ (i >> 4)) & 15); }

// 8-point DFT, natural-order outputs, in place.
__device__ __forceinline__ void dft8(float2* v) {
    const float2 t0 = cadd(v[0], v[4]), t1 = csub(v[0], v[4]);
    const float2 t2 = cadd(v[2], v[6]), t3 = csub(v[2], v[6]);
    const float2 E0 = cadd(t0, t2), E2 = csub(t0, t2);
    const float2 E1 = make_float2(t1.x + t3.y, t1.y - t3.x);
    const float2 E3 = make_float2(t1.x - t3.y, t1.y + t3.x);
    const float2 u0 = cadd(v[1], v[5]), u1 = csub(v[1], v[5]);
    const float2 u2 = cadd(v[3], v[7]), u3 = csub(v[3], v[7]);
    const float2 O0 = cadd(u0, u2), O2 = csub(u0, u2);
    const float2 O1 = make_float2(u1.x + u3.y, u1.y - u3.x);
    const float2 O3 = make_float2(u1.x - u3.y, u1.y + u3.x);
    const float2 w1O1 = make_float2(RQ * (O1.x + O1.y), RQ * (O1.y - O1.x));   // (1-i)r*O1
    const float2 w2O2 = make_float2(O2.y, -O2.x);                               // -i*O2
    const float2 w3O3 = make_float2(RQ * (O3.y - O3.x), -RQ * (O3.x + O3.y));  // (-1-i)r*O3
    v[0] = cadd(E0, O0);   v[4] = csub(E0, O0);
    v[1] = cadd(E1, w1O1); v[5] = csub(E1, w1O1);
    v[2] = cadd(E2, w2O2); v[6] = csub(E2, w2O2);
    v[3] = cadd(E3, w3O3); v[7] = csub(E3, w3O3);
}

// Radix-4 SMEM pass: stages (L, 2L). t2 = w_{2L}^j from LDS, w_L^j = t2^2.
template<int NFFT, int L, int TPF, int S>
__device__ __forceinline__ void radix4_pass(float2* buf, const float2* tw, int base, int ltid) {
    constexpr int BPT = (NFFT / 4) / TPF;
#pragma unroll
    for (int r = 0; r < BPT; r++) {
        const int idx = ltid + r * TPF;
        const int j   = idx & (L / 2 - 1);
        const int g   = idx / (L / 2);
        const int p   = base + g * (2 * L) + j;
        float2 a0 = buf[swz<S>(p)];
        float2 a1 = buf[swz<S>(p + L / 2)];
        float2 a2 = buf[swz<S>(p + L)];
        float2 a3 = buf[swz<S>(p + 3 * L / 2)];
        const float2 t2 = tw[j * (NFFT / (2 * L))];  // w_{2L}^j
        const float2 t1 = cmul(t2, t2);              // w_L^j
        const float2 u1 = cmul(t1, a1), u3 = cmul(t1, a3);
        const float2 c0 = cadd(a0, u1), c1 = csub(a0, u1);
        const float2 c2 = cadd(a2, u3), c3 = csub(a2, u3);
        const float2 v2 = cmul(t2, c2), v3 = cmul(t2, c3);
        buf[swz<S>(p)]             = cadd(c0, v2);
        buf[swz<S>(p + L)]         = csub(c0, v2);
        buf[swz<S>(p + L / 2)]     = make_float2(c1.x + v3.y, c1.y - v3.x);  // c1 - i*v3
        buf[swz<S>(p + 3 * L / 2)] = make_float2(c1.x - v3.y, c1.y + v3.x);  // c1 + i*v3
    }
}

// Radix-8 SMEM pass: stages (L, 2L, 4L) in one round trip.
// t4 = w_{4L}^j (one LDS); t2 = t4^2, t1 = t4^4 (exact identities).
template<int NFFT, int L, int TPF, int S>
__device__ __forceinline__ void radix8_pass(float2* buf, const float2* tw, int base, int ltid) {
    constexpr int BPT = (NFFT / 8) / TPF;
#pragma unroll
    for (int r = 0; r < BPT; r++) {
        const int idx = ltid + r * TPF;
        const int j   = idx & (L / 2 - 1);
        const int g   = idx / (L / 2);
        const int p   = base + g * (4 * L) + j;
        float2 b[8];
#pragma unroll
        for (int m = 0; m < 8; m++) b[m] = buf[swz<S>(p + m * (L / 2))];
        const float2 t4 = tw[j * (NFFT / (4 * L))];  // w_{4L}^j
        const float2 t2 = cmul(t4, t4);              // w_{2L}^j
        const float2 t1 = cmul(t2, t2);              // w_L^j
        float2 c[8];
#pragma unroll
        for (int m = 0; m < 4; m++) {
            const float2 u = cmul(t1, b[2 * m + 1]);
            c[2 * m]     = cadd(b[2 * m], u);
            c[2 * m + 1] = csub(b[2 * m], u);
        }
        float2 d[8];
        {
            const float2 tb = make_float2(t2.y, -t2.x);  // -i*t2
            float2 v;
            v = cmul(t2, c[2]); d[0] = cadd(c[0], v); d[2] = csub(c[0], v);
            v = cmul(tb, c[3]); d[1] = cadd(c[1], v); d[3] = csub(c[1], v);
            v = cmul(t2, c[6]); d[4] = cadd(c[4], v); d[6] = csub(c[4], v);
            v = cmul(tb, c[7]); d[5] = cadd(c[5], v); d[7] = csub(c[5], v);
        }
        {
            const float2 f1 = make_float2(RQ * (t4.x + t4.y), RQ * (t4.y - t4.x));   // t4*(1-i)r
            const float2 f2 = make_float2(t4.y, -t4.x);                               // t4*(-i)
            const float2 f3 = make_float2(RQ * (t4.y - t4.x), -RQ * (t4.x + t4.y));  // t4*(-1-i)r
            float2 v;
            v = cmul(t4, d[4]); buf[swz<S>(p)]             = cadd(d[0], v); buf[swz<S>(p + 4*(L/2))] = csub(d[0], v);
            v = cmul(f1, d[5]); buf[swz<S>(p + 1*(L/2))]   = cadd(d[1], v); buf[swz<S>(p + 5*(L/2))] = csub(d[1], v);
            v = cmul(f2, d[6]); buf[swz<S>(p + 2*(L/2))]   = cadd(d[2], v); buf[swz<S>(p + 6*(L/2))] = csub(d[2], v);
            v = cmul(f3, d[7]); buf[swz<S>(p + 3*(L/2))]   = cadd(d[3], v); buf[swz<S>(p + 7*(L/2))] = csub(d[3], v);
        }
    }
}

// ---------------------------------------------------------------------------
// Packed complex FFT (z = x + i*x_hat) over all frames of one scale.
// Load fuses windowing + first 3 stages (8-pt DFT); for N=1024 only, first 4
// stages (16-pt DFT) -> removes a block-wide-barrier SMEM round trip.
// (NOT for N<=256: there syncs are warp-level and load16 merely concentrates
// global-load latency in half the threads — measured regression in R16.)
// XOR bank swizzle on buf. TPF = NFFT/8; frame-scoped synchronization.
// ---------------------------------------------------------------------------
template<int NFFT, int OFF, int NBLK>
__device__ __forceinline__ void stft_body(const float* __restrict__ x,
                                          const float* __restrict__ xh,
                                          int blk, char* raw) {
    constexpr int  HOP    = NFFT / 4;
    constexpr int  PAD    = NFFT / 2;
    constexpr int  T      = 1 + NSAMP / HOP;
    constexpr int  TOTAL  = BATCH * T;
    constexpr int  F      = NFFT / 2 + 1;
    constexpr int  LOG2N  = ilog2c(NFFT);
    constexpr int  TPB    = 256;
    constexpr int  TPF    = (NFFT / 8 > TPB) ? TPB : (NFFT / 8);
    constexpr int  FPB    = TPB / TPF;
    constexpr int  KPT    = (F + TPF - 1) / TPF;
    constexpr int  BUFSZ  = FPB * NFFT;                // == 2048 for all scales
    static_assert(BUFSZ == 2048, "layout assumes BUFSZ==2048");
    constexpr int  S      = ilog2c(BUFSZ) - 4;
    constexpr bool LOAD16 = (LOG2N == 10);             // N=1024: 16-pt load stage

    float2* buf  = (float2*)raw;
    float2* tw   = (float2*)(raw + 16384);
    float*  win  = (float*)(raw + 16384 + 4 * NFFT);
    float*  red1 = (float*)(raw + 16384 + 8 * NFFT);
    float*  red2 = (float*)(raw + 16384 + 8 * NFFT + 4 * F);

    const int tid  = threadIdx.x;
    const int slot = tid / TPF;
    const int ltid = tid % TPF;
    const int base = slot * NFFT;

    auto sw = [](int i) { return swz<S>(i); };

    auto fsync = [&]() {
        if constexpr (TPF <= 32) { __syncwarp(); }
        else if constexpr (TPF >= TPB) { __syncthreads(); }
        else { asm volatile("bar.sync %0, %1;" :: "r"(slot + 1), "r"(TPF) : "memory"); }
    };

    // Twiddles: tw[t] = exp(-2*pi*i*t/N). Window: periodic hann / sqrt(0.375*N).
    const float rnorm = rsqrtf(0.375f * (float)NFFT);
    for (int t = tid; t < NFFT / 2; t += TPB) {
        float s, c;
        sincospif(2.0f * (float)t / (float)NFFT, &s, &c);
        tw[t] = make_float2(c, -s);
    }
    for (int t = tid; t < NFFT; t += TPB) {
        win[t] = (0.5f - 0.5f * cospif(2.0f * (float)t / (float)NFFT)) * rnorm;
    }
    for (int t = tid; t < F; t += TPB) { red1[t] = 0.0f; red2[t] = 0.0f; }

    float acc1[KPT], acc2[KPT];
#pragma unroll
    for (int r = 0; r < KPT; r++) { acc1[r] = 0.0f; acc2[r] = 0.0f; }

    __syncthreads();

    for (int fb = blk * FPB; fb < TOTAL; fb += NBLK * FPB) {
        const int gf = fb + slot;
        const bool valid = (gf < TOTAL);

        int start = 0;
        const float *xb = x, *xhb = xh;
        if (valid) {
            const int bb = gf / T;
            const int t0 = gf - bb * T;
            start = t0 * HOP - PAD;
            xb  = x  + bb * NSAMP;
            xhb = xh + bb * NSAMP;
        }

        auto load_one = [&](int tt) -> float2 {
            int s = start + tt;
            s = (s < 0) ? -s : s;                        // reflect left
            s = (s >= NSAMP) ? (2 * NSAMP - 2 - s) : s;  // reflect right
            const float wv = win[tt];
            return make_float2(xb[s] * wv, xhb[s] * wv);
        };

        if constexpr (!LOAD16) {
            // Load + window + 8-point DFT (stages 2,4,8).
            if (valid) {
                const int idx = ltid;                 // [0, N/8), TPF == N/8
                const int g   = (int)(__brev((unsigned)idx) >> (32 - (LOG2N - 3)));
                float2 a[8];
#pragma unroll
                for (int m = 0; m < 8; m++) a[m] = load_one(idx + m * (NFFT / 8));
                dft8(a);
                const int wb = base + 8 * g;
#pragma unroll
                for (int k = 0; k < 8; k++) buf[sw(wb + k)] = a[k];
            }
        } else {
            // Load + window + 16-point DFT (stages 2,4,8,16). N/16 groups,
            // handled by ltid < N/16 (half the frame's threads).
            if (valid && ltid < NFFT / 16) {
                const int idx = ltid;                 // [0, N/16)
                const int g   = (int)(__brev((unsigned)idx) >> (32 - (LOG2N - 4)));
                float2 ev[8], od[8];
#pragma unroll
                for (int m = 0; m < 8; m++) ev[m] = load_one(idx + m * (NFFT / 8));
                dft8(ev);
#pragma unroll
                for (int m = 0; m < 8; m++) od[m] = load_one(idx + NFFT / 16 + m * (NFFT / 8));
                dft8(od);
                // X[k] = ev[k] + w16^k od[k]; X[k+8] = ev[k] - w16^k od[k]
                const int wb = base + 16 * g;
                float2 t;
                buf[sw(wb + 0)] = cadd(ev[0], od[0]);
                buf[sw(wb + 8)] = csub(ev[0], od[0]);
                t = cmul(make_float2(C1, -S1), od[1]);
                buf[sw(wb + 1)] = cadd(ev[1], t);  buf[sw(wb + 9)]  = csub(ev[1], t);
                t = make_float2(RQ * (od[2].x + od[2].y), RQ * (od[2].y - od[2].x));
                buf[sw(wb + 2)] = cadd(ev[2], t);  buf[sw(wb + 10)] = csub(ev[2], t);
                t = cmul(make_float2(S1, -C1), od[3]);
                buf[sw(wb + 3)] = cadd(ev[3], t);  buf[sw(wb + 11)] = csub(ev[3], t);
                t = make_float2(od[4].y, -od[4].x);
                buf[sw(wb + 4)] = cadd(ev[4], t);  buf[sw(wb + 12)] = csub(ev[4], t);
                t = cmul(make_float2(-S1, -C1), od[5]);
                buf[sw(wb + 5)] = cadd(ev[5], t);  buf[sw(wb + 13)] = csub(ev[5], t);
                t = make_float2(RQ * (od[6].y - od[6].x), -RQ * (od[6].x + od[6].y));
                buf[sw(wb + 6)] = cadd(ev[6], t);  buf[sw(wb + 14)] = csub(ev[6], t);
                t = cmul(make_float2(-C1, -S1), od[7]);
                buf[sw(wb + 7)] = cadd(ev[7], t);  buf[sw(wb + 15)] = csub(ev[7], t);
            }
        }
        fsync();

        // Remaining stages: radix-8 / radix-4 passes.
        if constexpr (LOG2N == 5) {
            radix4_pass<NFFT, 16, TPF, S>(buf, tw, base, ltid); fsync();
        } else if constexpr (LOG2N == 6) {
            radix8_pass<NFFT, 16, TPF, S>(buf, tw, base, ltid); fsync();
        } else if constexpr (LOG2N == 7) {
            radix4_pass<NFFT, 16, TPF, S>(buf, tw, base, ltid); fsync();
            radix4_pass<NFFT, 64, TPF, S>(buf, tw, base, ltid); fsync();
        } else if constexpr (LOG2N == 8) {
            radix8_pass<NFFT, 16, TPF, S>(buf, tw, base, ltid); fsync();
            radix4_pass<NFFT, 128, TPF, S>(buf, tw, base, ltid); fsync();
        } else if constexpr (LOG2N == 9) {
            radix8_pass<NFFT, 16, TPF, S>(buf, tw, base, ltid); fsync();
            radix8_pass<NFFT, 128, TPF, S>(buf, tw, base, ltid); fsync();
        } else if constexpr (LOG2N == 10) {
            // load16 retired stages 2..16
            radix8_pass<NFFT, 32, TPF, S>(buf, tw, base, ltid); fsync();
            radix8_pass<NFFT, 256, TPF, S>(buf, tw, base, ltid); fsync();
        } else {
            radix8_pass<NFFT, 16, TPF, S>(buf, tw, base, ltid); fsync();
            radix8_pass<NFFT, 128, TPF, S>(buf, tw, base, ltid); fsync();
            radix4_pass<NFFT, 1024, TPF, S>(buf, tw, base, ltid); fsync();
        }

        // Unpack X (from x) and Xh (from x_hat), accumulate stats
        if (valid) {
#pragma unroll
            for (int r = 0; r < KPT; r++) {
                const int k = ltid + r * TPF;
                if (k <= NFFT / 2) {
                    const float2 zk = buf[sw(base + k)];
                    const float2 zn = buf[sw(base + ((NFFT - k) & (NFFT - 1)))];
                    const float ar = 0.5f * (zk.x + zn.x);
                    const float ai = 0.5f * (zk.y - zn.y);
                    const float br = 0.5f * (zk.y + zn.y);
                    const float bi = 0.5f * (zn.x - zk.x);
                    const float magA = sqrtf(ar * ar + ai * ai);
                    const float magB = sqrtf(br * br + bi * bi);
                    const float d = magB - magA;          // |Xh| - |X|
                    acc1[r] += fabsf(d);
                    acc2[r] += d * d;
                }
            }
        }
        fsync();   // protect buf before next load (frame-scoped)
    }

    // Block reduce: registers -> shared float
#pragma unroll
    for (int r = 0; r < KPT; r++) {
        const int k = ltid + r * TPF;
        if (k <= NFFT / 2) {
            atomicAdd(&red1[k], acc1[r]);
            atomicAdd(&red2[k], acc2[r]);
        }
    }
    __syncthreads();

    for (int k = tid; k < F; k += TPB) {
        atomicAdd(&g_s1[OFF + k], (double)red1[k]);
        atomicAdd(&g_s2[OFF + k], (double)red2[k]);
    }
}

// All 7 scales, one persistent wave; min 4 blocks/SM (<=64 regs).
// Shares: {65,65,86,86,86,97,107} (cost-balanced, sum 592).
__global__ void __launch_bounds__(256, 4)
fused_stft(const float* __restrict__ x, const float* __restrict__ xh) {
    extern __shared__ char raw[];
    const int b = blockIdx.x;
    if      (b <  65) stft_body<  32,    0,  65>(x, xh, b,       raw);
    else if (b < 130) stft_body<  64,   17,  65>(x, xh, b - 65,  raw);
    else if (b < 216) stft_body< 128,   50,  86>(x, xh, b - 130, raw);
    else if (b < 302) stft_body< 256,  115,  86>(x, xh, b - 216, raw);
    else if (b < 388) stft_body< 512,  244,  86>(x, xh, b - 302, raw);
    else if (b < 485) stft_body<1024,  501,  97>(x, xh, b - 388, raw);
    else              stft_body<2048, 1014, 107>(x, xh, b - 485, raw);
}

// ---------------------------------------------------------------------------
// Loss: 7 blocks (one per scale). fpts[0..64] via cheap fp64 exp2 (error ~2ulp
// vs >=1e-9 margins); index 65 keeps the bit-exact libdevice pow + the verified
// Nyquist flip in an otherwise-empty warp. Band-edge decisions unchanged.
// ---------------------------------------------------------------------------
__global__ void __launch_bounds__(256) loss_kernel(float* out) {
    const int s    = blockIdx.x;
    const int tid  = threadIdx.x;
    const int w    = tid >> 5;
    const int lane = tid & 31;
    const int NFFT = 32 << s;
    const int F    = NFFT / 2 + 1;

    __shared__ double fpts[66];
    __shared__ int2   sab[64];
    __shared__ double ssum;
    if (tid == 0) ssum = 0.0;

    const double melmax = 2595.0 * log10(1.0 + 12000.0 / 700.0);
    if (tid < 65) {
        const double e = melmax * (double)tid / 65.0 / 2595.0;
        fpts[tid] = 700.0 * (exp2(e * 3.3219280948873623478703194) - 1.0);
    } else if (tid == 96) {
        // index 65: exact libdevice pow expression (bit-identical to verified)
        fpts[65] = 700.0 * (pow(10.0, opaque_d(melmax * 65.0 / 65.0) / 2595.0) - 1.0);
    }
    __syncthreads();

    bool keep = false;
    if (tid < 64) {
        const int m = tid;
        const double step = 12000.0 / (double)(F - 1);
        const bool nyq_in = !(fpts[65] > 12000.0);   // flipped libdevice decision (verified)

        int a[2], b[2];   // [0] = band m, [1] = band m-1
        for (int q = 0; q < 2; q++) {
            const int mm = m - q;
            if (mm < 0) { a[q] = 0; b[q] = 0; continue; }
            const double lo = fpts[mm];
            int a0 = (int)floor(lo / step); if ((double)a0 * step <= lo) a0++;  // first f: f*step > lo
            if (a0 < 0) a0 = 0;
            int b0;
            if (mm + 2 == 65) {
                b0 = nyq_in ? F : (F - 1);
            } else {
                const double hi = fpts[mm + 2];
                b0 = (int)floor(hi / step); if ((double)b0 * step <  hi) b0++;  // last f+1: f*step < hi
                if (b0 > F) b0 = F;
            }
            a[q] = a0; b[q] = b0;
        }
        const bool nonempty = (b[0] > a[0]);
        const bool dup = (m > 0) && (a[0] == a[1]) && (b[0] == b[1]) && nonempty;
        keep = nonempty && !dup;
        sab[m] = keep ? make_int2(a[0], b[0]) : make_int2(0, 0);
    }
    const int nb = __syncthreads_count(keep ? 1 : 0);

    for (int cand = w; cand < 64; cand += 8) {
        const int2 ab = sab[cand];
        if (ab.y > ab.x) {
            double p1 = 0.0, p2 = 0.0;
            for (int f = ab.x + lane; f < ab.y; f += 32) {
                p1 += g_s1[c_soff[s] + f];
                p2 += g_s2[c_soff[s] + f];
            }
#pragma unroll
            for (int o = 16; o > 0; o >>= 1) {
                p1 += __shfl_down_sync(0xffffffffu, p1, o);
                p2 += __shfl_down_sync(0xffffffffu, p2, o);
            }
            if (lane == 0) {
                const double cnt = (double)(ab.y - ab.x) * (double)BATCH * (double)c_T[s];
                const double val = p1 / cnt + sqrt(p2 / cnt + 1e-8);
                atomicAdd(&ssum, val);
            }
        }
    }
    __syncthreads();

    if (tid == 0) {
        double* acc  = g_blob + 2 * TOTF;
        int*    done = (int*)(g_blob + 2 * TOTF + 1);
        const double contrib = ssum / (double)nb / 7.0;
        atomicAdd(acc, contrib);
        __threadfence();
        const int old = atomicAdd(done, 1);
        if (old == 6) {
            out[0] = (float)(*(volatile double*)acc);
        }
    }
}

extern "C" void kernel_launch(void* const* d_in, const int* in_sizes, int n_in,
                              void* d_out, int out_size) {
    const float* xh = (const float*)d_in[0];   // x_hat
    const float* x  = (const float*)d_in[1];   // x

    void* pb = nullptr;
    cudaGetSymbolAddress(&pb, g_blob);
    cudaMemsetAsync(pb, 0, (2 * TOTF + 2) * sizeof(double));

    fused_stft<<<NBLOCKS, 256, SMEM_DYN>>>(x, xh);
    loss_kernel<<<7, 256>>>((float*)d_out);
}